// round 6
// baseline (speedup 1.0000x reference)
#include <cuda_runtime.h>
#include <cuda_bf16.h>
#include <cstdint>

#define B_ROWS 8192
#define P_DIM 512
#define C_CLASSES 1000
#define C_PAD 1024

#define BM 128
#define BN 128
#define BK 64
#define NCHUNK (P_DIM / BK)   // 8
#define NSTAGE 3
#define LDA 72                 // BK + 8 pad: 144B row stride, conflict-free LDSM
#define LDB 72

#define A_STAGE_BYTES (BM * LDA * 2)   // 18432
#define B_STAGE_BYTES (BN * LDB * 2)   // 18432
#define STAGE_BYTES (A_STAGE_BYTES + B_STAGE_BYTES)   // 36864
#define SMEM_TOTAL (NSTAGE * STAGE_BYTES + 16)        // 110608 -> 2 CTAs/SM

#define N_TILES 512            // (C_PAD/BN) * (B_ROWS/BM) = 8 * 64
#define GRID_CTAS 296          // 148 SMs * 2 CTAs

// ---- scratch (device globals; no allocation allowed) ----
__device__ __nv_bfloat16 g_xb[B_ROWS * P_DIM];
__device__ __nv_bfloat16 g_mb[C_PAD * P_DIM];
__device__ float g_rx[B_ROWS];
__device__ float g_xsq[B_ROWS];
__device__ float g_msq[C_PAD];
__device__ unsigned g_tile_ctr;

// ======================= PTX helpers =======================
__device__ __forceinline__ uint32_t smem_u32(const void* p) {
    uint32_t a;
    asm("{ .reg .u64 t; cvta.to.shared.u64 t, %1; cvt.u32.u64 %0, t; }" : "=r"(a) : "l"(p));
    return a;
}
__device__ __forceinline__ void cp_async16(uint32_t dst, const void* src) {
    asm volatile("cp.async.cg.shared.global [%0], [%1], 16;" :: "r"(dst), "l"(src) : "memory");
}
__device__ __forceinline__ void cp_commit() {
    asm volatile("cp.async.commit_group;" ::: "memory");
}
__device__ __forceinline__ void cp_wait1() {
    asm volatile("cp.async.wait_group 1;" ::: "memory");
}
__device__ __forceinline__ void cp_wait0() {
    asm volatile("cp.async.wait_group 0;" ::: "memory");
}
__device__ __forceinline__ void ldsm_x4(uint32_t& r0, uint32_t& r1, uint32_t& r2, uint32_t& r3,
                                        uint32_t addr) {
    asm volatile("ldmatrix.sync.aligned.m8n8.x4.shared.b16 {%0,%1,%2,%3}, [%4];"
                 : "=r"(r0), "=r"(r1), "=r"(r2), "=r"(r3) : "r"(addr));
}
__device__ __forceinline__ void mma16816(float c[4], const uint32_t a[4], const uint32_t b[2]) {
    asm volatile(
        "mma.sync.aligned.m16n8k16.row.col.f32.bf16.bf16.f32 "
        "{%0,%1,%2,%3}, {%4,%5,%6,%7}, {%8,%9}, {%0,%1,%2,%3};\n"
        : "+f"(c[0]), "+f"(c[1]), "+f"(c[2]), "+f"(c[3])
        : "r"(a[0]), "r"(a[1]), "r"(a[2]), "r"(a[3]), "r"(b[0]), "r"(b[1]));
}

// ======================= fused prep kernel =======================
// blocks [0,128): class rows (8/block).  blocks [128,1152): x rows (8/block).
__global__ void prep_all(const float* __restrict__ x, const float* __restrict__ means) {
    const int wid = threadIdx.x >> 5, lane = threadIdx.x & 31;

    if (blockIdx.x < 128) {
        const int c = blockIdx.x * 8 + wid;
        float4 v[4];
        float ss = 0.0f;
        if (c < C_CLASSES) {
            const float4* src = (const float4*)(means + (size_t)c * P_DIM);
            #pragma unroll
            for (int i = 0; i < 4; i++) {
                v[i] = src[lane + i * 32];
                ss += v[i].x * v[i].x + v[i].y * v[i].y + v[i].z * v[i].z + v[i].w * v[i].w;
            }
        } else {
            #pragma unroll
            for (int i = 0; i < 4; i++) v[i] = make_float4(0.f, 0.f, 0.f, 0.f);
        }
        #pragma unroll
        for (int o = 16; o > 0; o >>= 1) ss += __shfl_xor_sync(0xffffffffu, ss, o);

        uint2* dst = (uint2*)(g_mb + (size_t)c * P_DIM);
        #pragma unroll
        for (int i = 0; i < 4; i++) {
            __nv_bfloat162 lo = __floats2bfloat162_rn(v[i].x, v[i].y);
            __nv_bfloat162 hi = __floats2bfloat162_rn(v[i].z, v[i].w);
            uint2 p; p.x = *(uint32_t*)&lo; p.y = *(uint32_t*)&hi;
            dst[lane + i * 32] = p;
        }
        if (lane == 0) g_msq[c] = ss;
    } else {
        const int b = (blockIdx.x - 128) * 8 + wid;
        // per-warp redundant scale = ||means[0]|| (row 0 is L2-hot)
        float sc = 0.0f;
        {
            const float4* m0 = (const float4*)means;
            #pragma unroll
            for (int i = 0; i < 4; i++) {
                float4 m = m0[lane + i * 32];
                sc += m.x * m.x + m.y * m.y + m.z * m.z + m.w * m.w;
            }
            #pragma unroll
            for (int o = 16; o > 0; o >>= 1) sc += __shfl_xor_sync(0xffffffffu, sc, o);
            sc = sqrtf(sc);
        }

        const float4* src = (const float4*)(x + (size_t)b * P_DIM);
        float4 v[4];
        float ss = 0.0f;
        #pragma unroll
        for (int i = 0; i < 4; i++) {
            v[i] = src[lane + i * 32];
            ss += v[i].x * v[i].x + v[i].y * v[i].y + v[i].z * v[i].z + v[i].w * v[i].w;
        }
        #pragma unroll
        for (int o = 16; o > 0; o >>= 1) ss += __shfl_xor_sync(0xffffffffu, ss, o);

        uint2* dst = (uint2*)(g_xb + (size_t)b * P_DIM);
        #pragma unroll
        for (int i = 0; i < 4; i++) {
            __nv_bfloat162 lo = __floats2bfloat162_rn(v[i].x, v[i].y);
            __nv_bfloat162 hi = __floats2bfloat162_rn(v[i].z, v[i].w);
            uint2 p; p.x = *(uint32_t*)&lo; p.y = *(uint32_t*)&hi;
            dst[lane + i * 32] = p;
        }
        if (lane == 0) {
            float norm = sqrtf(ss);
            float r = sc / (norm + 1e-10f);
            g_rx[b] = r;
            float tn = norm * r;
            g_xsq[b] = tn * tn;
        }
    }
}

// ======================= persistent pipelined HMMA GEMM =======================
// 296 persistent CTAs (2/SM), dynamic tile stealing over 512 tiles of 128x128.
// 256 threads = 8 warps in 4(m) x 2(n); warptile 32 x 64.
__global__ __launch_bounds__(256, 2) void gemm_logits(float* __restrict__ out) {
    extern __shared__ __align__(16) char smem_raw[];
    const uint32_t sbase = smem_u32(smem_raw);
    unsigned* tile_bcast = (unsigned*)(smem_raw + NSTAGE * STAGE_BYTES);

    const int t = threadIdx.x;
    const int warp = t >> 5, lane = t & 31;
    const int wm = warp & 3;    // m-warp 0..3
    const int wn = warp >> 2;   // n-warp 0..1
    const int grp = lane >> 2, tid4 = lane & 3;

    // tile-invariant per-thread cp.async mapping (8 chunks of 16B per thread)
    // i 0..3 -> A (g_xb), i 4..7 -> B (g_mb); row = v>>3, colchunk = (v&7)*8
    size_t src_inv[8];
    uint32_t dsts[8];
    #pragma unroll
    for (int i = 0; i < 8; i++) {
        int v = t + i * 256;
        int v2 = v & 1023;
        int r = v2 >> 3, cc = (v2 & 7) * 8;
        src_inv[i] = (size_t)r * P_DIM + cc;
        dsts[i] = (uint32_t)(r * (i < 4 ? LDA : LDB) + cc) * 2 + (i < 4 ? 0u : (uint32_t)A_STAGE_BYTES);
    }

    // LDSM lane addressing (tile-invariant)
    const int lq = lane >> 3, lr = lane & 7;
    const uint32_t a_lane_off =
        (uint32_t)((wm * 32 + (lq & 1) * 8 + lr) * LDA + (lq >> 1) * 8) * 2;
    const uint32_t b_lane_off =
        A_STAGE_BYTES + (uint32_t)((wn * 64 + (lq >> 1) * 8 + lr) * LDB + (lq & 1) * 8) * 2;

    for (;;) {
        if (t == 0) *tile_bcast = atomicAdd(&g_tile_ctr, 1u);
        __syncthreads();                // also fences prior tile's stage reads
        const unsigned tile = *tile_bcast;
        if (tile >= N_TILES) break;

        const int bm = (int)(tile >> 3) * BM;        // 64 m-blocks
        const int bn = (int)(tile & 7) * BN;         // 8 n-blocks

        const __nv_bfloat16* srcs[8];
        #pragma unroll
        for (int i = 0; i < 8; i++)
            srcs[i] = (i < 4 ? g_xb + (size_t)bm * P_DIM : g_mb + (size_t)bn * P_DIM) + src_inv[i];

        float acc[2][8][4];
        #pragma unroll
        for (int mi = 0; mi < 2; mi++)
            #pragma unroll
            for (int ni = 0; ni < 8; ni++)
                #pragma unroll
                for (int q = 0; q < 4; q++) acc[mi][ni][q] = 0.0f;

        auto issue_stage = [&](int c) {
            const uint32_t st = sbase + (c % NSTAGE) * STAGE_BYTES;
            const int koff = c * BK;
            #pragma unroll
            for (int i = 0; i < 8; i++)
                cp_async16(st + dsts[i], srcs[i] + koff);
        };

        issue_stage(0); cp_commit();
        issue_stage(1); cp_commit();

        #pragma unroll 1
        for (int c = 0; c < NCHUNK; c++) {
            if (c == NCHUNK - 1) cp_wait0(); else cp_wait1();
            __syncthreads();            // stage (c-1)%3 reusable by all warps

            if (c + 2 < NCHUNK) { issue_stage(c + 2); cp_commit(); }

            const uint32_t st = sbase + (c % NSTAGE) * STAGE_BYTES;
            const uint32_t ast = st + a_lane_off;
            const uint32_t bst = st + b_lane_off;

            #pragma unroll
            for (int kk = 0; kk < BK; kk += 16) {
                uint32_t a[2][4];
                #pragma unroll
                for (int mi = 0; mi < 2; mi++)
                    ldsm_x4(a[mi][0], a[mi][1], a[mi][2], a[mi][3],
                            ast + (uint32_t)(mi * 16 * LDA + kk) * 2);
                uint32_t b[8][2];
                #pragma unroll
                for (int ng = 0; ng < 4; ng++)
                    ldsm_x4(b[ng * 2][0], b[ng * 2][1], b[ng * 2 + 1][0], b[ng * 2 + 1][1],
                            bst + (uint32_t)(ng * 16 * LDB + kk) * 2);
                #pragma unroll
                for (int mi = 0; mi < 2; mi++)
                    #pragma unroll
                    for (int ni = 0; ni < 8; ni++)
                        mma16816(acc[mi][ni], a[mi], b[ni]);
            }
        }

        // ---- fused epilogue: out = 2*r_b*dot - xsq_b - msq_c ----
        #pragma unroll
        for (int mi = 0; mi < 2; mi++) {
            int row0 = bm + wm * 32 + mi * 16 + grp;
            float r0f = g_rx[row0], xs0 = g_xsq[row0];
            float r1f = g_rx[row0 + 8], xs1 = g_xsq[row0 + 8];
            #pragma unroll
            for (int ni = 0; ni < 8; ni++) {
                int col = bn + wn * 64 + ni * 8 + tid4 * 2;
                if (col < C_CLASSES) {
                    float ms = g_msq[col];
                    out[(size_t)row0 * C_CLASSES + col]       = 2.0f * r0f * acc[mi][ni][0] - xs0 - ms;
                    out[(size_t)(row0 + 8) * C_CLASSES + col] = 2.0f * r1f * acc[mi][ni][2] - xs1 - ms;
                }
                if (col + 1 < C_CLASSES) {
                    float ms = g_msq[col + 1];
                    out[(size_t)row0 * C_CLASSES + col + 1]       = 2.0f * r0f * acc[mi][ni][1] - xs0 - ms;
                    out[(size_t)(row0 + 8) * C_CLASSES + col + 1] = 2.0f * r1f * acc[mi][ni][3] - xs1 - ms;
                }
            }
        }
    }
}

extern "C" void kernel_launch(void* const* d_in, const int* in_sizes, int n_in,
                              void* d_out, int out_size) {
    const float* x = (const float*)d_in[0];      // (8192, 512)
    const float* means = (const float*)d_in[1];  // (1000, 512)
    float* out = (float*)d_out;                  // (8192, 1000)
    (void)in_sizes; (void)n_in; (void)out_size;

    static void* ctr_addr = nullptr;
    static int smem_set = 0;
    if (!smem_set) {
        cudaFuncSetAttribute(gemm_logits, cudaFuncAttributeMaxDynamicSharedMemorySize, SMEM_TOTAL);
        cudaGetSymbolAddress(&ctr_addr, g_tile_ctr);
        smem_set = 1;
    }

    cudaMemsetAsync(ctr_addr, 0, sizeof(unsigned), 0);   // graph-capturable memset node
    prep_all<<<128 + B_ROWS / 8, 256>>>(x, means);
    gemm_logits<<<GRID_CTAS, 256, SMEM_TOTAL>>>(out);
}